// round 8
// baseline (speedup 1.0000x reference)
#include <cuda_runtime.h>
#include <math.h>

#define ROWS    32768
#define COLS    1024
#define D_IN    256
#define D_OUT   256
#define D_CTRL  1024
#define D_CIN   1280      // D_IN + COLS
#define HEADSZ  1030      // COLS + 1 + 1 + 3 + 1
#define N_PAR   4108      // 2*HEADSZ + 2*COLS
#define NBF     2048      // blocks in final pass
#define RPB     16        // rows per block in final pass

// ---------------- device scratch (static: no allocations allowed) -----------
__device__ float g_h[D_CTRL];
__device__ float g_p[N_PAR];
__device__ float g_krn[COLS], g_kwn[COLS], g_e[COLS], g_a[COLS];
__device__ float g_scal[12];          // per head: beta, g, s0, s1, s2, gamma
__device__ float g_red[4];            // sumexp_r, sumexp_w, powsum_r, powsum_w
__device__ float g_z[2][ROWS];        // exp(beta*cos - beta) per head
__device__ float g_wpow[2][ROWS];     // pre-normalization sharpened weights
__device__ float g_part[NBF * COLS];  // read_vec block partials (8 MB)

// ---------------- helpers ----------------------------------------------------
__device__ __forceinline__ float sigmoidf_(float x) { return 1.f / (1.f + expf(-x)); }
__device__ __forceinline__ float softplusf_(float x) { return x > 20.f ? x : log1pf(expf(x)); }

__device__ __forceinline__ float warp_sum(float v) {
    #pragma unroll
    for (int o = 16; o; o >>= 1) v += __shfl_down_sync(0xffffffffu, v, o);
    return v;
}

// block-wide sum for 1024 threads; red must be shared float[33]
__device__ float block_sum_1024(float v, float* red) {
    int t = threadIdx.x;
    v = warp_sum(v);
    if ((t & 31) == 0) red[t >> 5] = v;
    __syncthreads();
    if (t < 32) {
        float u = red[t];
        u = warp_sum(u);
        if (t == 0) red[32] = u;
    }
    __syncthreads();
    return red[32];
}

// ---------------- K1: h = Wc @ [x; read_prev] + bc --------------------------
__global__ void k_gemv_h(const float* __restrict__ x, const float* __restrict__ rp,
                         const float* __restrict__ Wc, const float* __restrict__ bc) {
    int warp = (blockIdx.x * blockDim.x + threadIdx.x) >> 5;
    int lane = threadIdx.x & 31;
    if (warp >= D_CTRL) return;
    const float4* W4 = (const float4*)(Wc + (size_t)warp * D_CIN);
    const float4* x4 = (const float4*)x;
    const float4* r4 = (const float4*)rp;
    float s = 0.f;
    #pragma unroll
    for (int k = 0; k < 10; k++) {
        int c = lane + 32 * k;                 // float4 index 0..319
        float4 w = __ldcs(&W4[c]);
        float4 v = (c < 64) ? x4[c] : r4[c - 64];
        s += w.x * v.x + w.y * v.y + w.z * v.z + w.w * v.w;
    }
    s = warp_sum(s);
    if (lane == 0) g_h[warp] = s + bc[warp];
}

// ---------------- K2: p = Wp @ h + bp ; saida = sigmoid(Wo @ h + bo) ---------
__global__ void k_gemv_p(const float* __restrict__ Wp, const float* __restrict__ bp,
                         const float* __restrict__ Wo, const float* __restrict__ bo,
                         float* __restrict__ o_saida) {
    int warp = (blockIdx.x * blockDim.x + threadIdx.x) >> 5;
    int lane = threadIdx.x & 31;
    if (warp >= N_PAR + D_OUT) return;
    const float4* W4 = (warp < N_PAR)
        ? (const float4*)(Wp + (size_t)warp * D_CTRL)
        : (const float4*)(Wo + (size_t)(warp - N_PAR) * D_CTRL);
    const float4* h4 = (const float4*)g_h;
    float s = 0.f;
    #pragma unroll
    for (int k = 0; k < 8; k++) {
        int c = lane + 32 * k;
        float4 w = __ldcs(&W4[c]), v = h4[c];
        s += w.x * v.x + w.y * v.y + w.z * v.z + w.w * v.w;
    }
    s = warp_sum(s);
    if (lane == 0) {
        if (warp < N_PAR) g_p[warp] = s + bp[warp];
        else o_saida[warp - N_PAR] = sigmoidf_(s + bo[warp - N_PAR]);
    }
}

// ---------------- K3: activations, key normalization, scalars, reset reds ---
__global__ void k_activ() {
    __shared__ float red[33];
    int t = threadIdx.x;  // 1024 threads

    float kr = tanhf(g_p[t]);
    float nr = block_sum_1024(kr * kr, red);
    float kw = tanhf(g_p[HEADSZ + t]);
    float nw = block_sum_1024(kw * kw, red);

    g_krn[t] = kr / fmaxf(sqrtf(nr), 1e-12f);
    g_kwn[t] = kw / fmaxf(sqrtf(nw), 1e-12f);
    g_e[t]   = sigmoidf_(g_p[2 * HEADSZ + t]);
    g_a[t]   = tanhf(g_p[2 * HEADSZ + COLS + t]);

    if (t < 2) {
        int o = t * HEADSZ;
        float beta  = softplusf_(g_p[o + COLS]);
        float gg    = sigmoidf_(g_p[o + COLS + 1]);
        float a0 = g_p[o + COLS + 2], a1 = g_p[o + COLS + 3], a2 = g_p[o + COLS + 4];
        float m = fmaxf(a0, fmaxf(a1, a2));
        float e0 = expf(a0 - m), e1 = expf(a1 - m), e2 = expf(a2 - m);
        float inv = 1.f / (e0 + e1 + e2);
        float gamma = softplusf_(g_p[o + COLS + 5]) + 1.f;
        g_scal[t * 6 + 0] = beta;
        g_scal[t * 6 + 1] = gg;
        g_scal[t * 6 + 2] = e0 * inv;
        g_scal[t * 6 + 3] = e1 * inv;
        g_scal[t * 6 + 4] = e2 * inv;
        g_scal[t * 6 + 5] = gamma;
    }
    if (t < 4) g_red[t] = 0.f;
}

// ---------------- K4: similarity pass (128 MB read) --------------------------
// Keys in smem, 4 rows/warp, k-unroll x2 -> 8 LDG.128 in flight per warp.
// DEFAULT loads (no __ldcs): leaves the tail of memoria resident in L2
// (~126 MB) so the reversed-order k_final read stream hits L2.
__global__ void __launch_bounds__(256, 5) k_sim(const float* __restrict__ mem) {
    __shared__ float4 skr[256], skw[256];
    __shared__ float ser[8], sew[8];
    int t = threadIdx.x;
    skr[t] = ((const float4*)g_krn)[t];
    skw[t] = ((const float4*)g_kwn)[t];
    __syncthreads();

    int warp = t >> 5, lane = t & 31;
    int row0 = (blockIdx.x * 8 + warp) * 4;
    const float4* m0 = (const float4*)mem + (size_t)row0 * 256;

    float dr[4], dw[4], ss[4];
    #pragma unroll
    for (int j = 0; j < 4; j++) { dr[j] = 0.f; dw[j] = 0.f; ss[j] = 0.f; }

    #pragma unroll
    for (int k = 0; k < 8; k += 2) {
        int c0 = lane + 32 * k, c1 = c0 + 32;
        float4 a[4][2];
        #pragma unroll
        for (int j = 0; j < 4; j++) {
            a[j][0] = m0[(size_t)j * 256 + c0];
            a[j][1] = m0[(size_t)j * 256 + c1];
        }
        float4 r0 = skr[c0], r1 = skr[c1];
        float4 w0 = skw[c0], w1 = skw[c1];
        #pragma unroll
        for (int j = 0; j < 4; j++) {
            float4 v = a[j][0];
            dr[j] += v.x * r0.x + v.y * r0.y + v.z * r0.z + v.w * r0.w;
            dw[j] += v.x * w0.x + v.y * w0.y + v.z * w0.z + v.w * w0.w;
            ss[j] += v.x * v.x + v.y * v.y + v.z * v.z + v.w * v.w;
            v = a[j][1];
            dr[j] += v.x * r1.x + v.y * r1.y + v.z * r1.z + v.w * r1.w;
            dw[j] += v.x * w1.x + v.y * w1.y + v.z * w1.z + v.w * w1.w;
            ss[j] += v.x * v.x + v.y * v.y + v.z * v.z + v.w * v.w;
        }
    }
    #pragma unroll
    for (int j = 0; j < 4; j++) {
        dr[j] = warp_sum(dr[j]);
        dw[j] = warp_sum(dw[j]);
        ss[j] = warp_sum(ss[j]);
    }
    if (lane == 0) {
        float br = g_scal[0], bw = g_scal[6];
        float sr = 0.f, sw = 0.f;
        #pragma unroll
        for (int j = 0; j < 4; j++) {
            float inv = 1.f / fmaxf(sqrtf(ss[j]), 1e-12f);
            // z = beta*cos; subtract analytic bound beta (cos <= 1) for stability
            float er = expf(br * dr[j] * inv - br);
            float ew = expf(bw * dw[j] * inv - bw);
            g_z[0][row0 + j] = er;
            g_z[1][row0 + j] = ew;
            sr += er; sw += ew;
        }
        ser[warp] = sr; sew[warp] = sw;
    }
    __syncthreads();
    if (t == 0) {
        float sr = 0.f, sw = 0.f;
        #pragma unroll
        for (int i = 0; i < 8; i++) { sr += ser[i]; sw += sew[i]; }
        atomicAdd(&g_red[0], sr);
        atomicAdd(&g_red[1], sw);
    }
}

// ---------------- K5: gate + circular shift + sharpening (both heads) -------
__global__ void k_shiftpow(const float* __restrict__ wpr, const float* __restrict__ wpw) {
    __shared__ float red[8];
    int head = blockIdx.y;
    int i = blockIdx.x * 256 + threadIdx.x;
    const float* wprev = head ? wpw : wpr;
    const float* z = g_z[head];
    float invsum = 1.f / g_red[head];
    float gg = g_scal[head * 6 + 1];
    float s0 = g_scal[head * 6 + 2], s1 = g_scal[head * 6 + 3], s2 = g_scal[head * 6 + 4];
    float gamma = g_scal[head * 6 + 5];
    float omg = 1.f - gg;

    int im = (i - 1) & (ROWS - 1), ip = (i + 1) & (ROWS - 1);
    float wgm = gg * z[im] * invsum + omg * wprev[im];
    float wg0 = gg * z[i]  * invsum + omg * wprev[i];
    float wgp = gg * z[ip] * invsum + omg * wprev[ip];
    float wt = s0 * wgm + s1 * wg0 + s2 * wgp;   // roll(+1)=i-1, roll(-1)=i+1
    float wp = powf(wt, gamma);
    g_wpow[head][i] = wp;

    wp = warp_sum(wp);
    if ((threadIdx.x & 31) == 0) red[threadIdx.x >> 5] = wp;
    __syncthreads();
    if (threadIdx.x == 0) {
        float s = 0.f;
        #pragma unroll
        for (int w = 0; w < 8; w++) s += red[w];
        atomicAdd(&g_red[2 + head], s);
    }
}

// ---------------- K6: final pass — reversed order for L2 reuse --------------
// Blocks walk memoria in REVERSE row order: the rows k_sim touched last are
// still L2-resident (memoria ~= L2 capacity), so the read stream hits L2.
// Loads default (cacheable); stores streaming (evict-first) to limit
// self-pollution. Double-buffered 4-row pipeline, thread-owns-columns,
// read_vec partial -> g_part (no atomics).
__global__ void __launch_bounds__(256) k_final(const float* __restrict__ mem,
                                               float* __restrict__ memnew,
                                               float* __restrict__ o_wr,
                                               float* __restrict__ o_ww) {
    int t = threadIdx.x;
    int row0 = (int)(gridDim.x - 1 - blockIdx.x) * RPB;  // reversed
    float inv_r = 1.f / (g_red[2] + 1e-8f);
    float inv_w = 1.f / (g_red[3] + 1e-8f);

    if (t < RPB) {
        int r = row0 + t;
        o_wr[r] = g_wpow[0][r] * inv_r;
        o_ww[r] = g_wpow[1][r] * inv_w;
    }

    float4 e = ((const float4*)g_e)[t];
    float4 a = ((const float4*)g_a)[t];
    float4 acc = make_float4(0.f, 0.f, 0.f, 0.f);

    const float4* m4 = (const float4*)mem + (size_t)row0 * 256 + t;
    float4* o4 = (float4*)memnew + (size_t)row0 * 256 + t;

    float4 buf[2][4];
    #pragma unroll
    for (int j = 0; j < 4; j++) buf[0][j] = m4[(size_t)j * 256];

    #pragma unroll
    for (int r = 0; r < RPB; r += 4) {
        const int cur = (r >> 2) & 1, nxt = cur ^ 1;
        if (r + 4 < RPB) {
            #pragma unroll
            for (int j = 0; j < 4; j++)
                buf[nxt][j] = m4[(size_t)(r + 4 + j) * 256];
        }
        #pragma unroll
        for (int j = 0; j < 4; j++) {
            int row = row0 + r + j;
            float wr = g_wpow[0][row] * inv_r;
            float ww = g_wpow[1][row] * inv_w;
            float4 m = buf[cur][j];
            float4 o;
            o.x = m.x * (1.f - ww * e.x) + ww * a.x;
            o.y = m.y * (1.f - ww * e.y) + ww * a.y;
            o.z = m.z * (1.f - ww * e.z) + ww * a.z;
            o.w = m.w * (1.f - ww * e.w) + ww * a.w;
            __stcs(o4 + (size_t)(r + j) * 256, o);
            acc.x += wr * m.x;
            acc.y += wr * m.y;
            acc.z += wr * m.z;
            acc.w += wr * m.w;
        }
    }
    ((float4*)g_part)[(size_t)blockIdx.x * 256 + t] = acc;
}

// ---------------- K7: reduce read_vec partials -------------------------------
// Block b owns float4-column b (cols 4b..4b+3); sums NBF partials.
__global__ void __launch_bounds__(256) k_rv(float* __restrict__ rv) {
    __shared__ float4 sh[256];
    int b = blockIdx.x;      // 0..255
    int t = threadIdx.x;
    const float4* p4 = (const float4*)g_part;
    float4 s = make_float4(0.f, 0.f, 0.f, 0.f);
    #pragma unroll
    for (int i = 0; i < NBF / 256; i++) {
        float4 v = p4[(size_t)(t + i * 256) * 256 + b];
        s.x += v.x; s.y += v.y; s.z += v.z; s.w += v.w;
    }
    sh[t] = s;
    __syncthreads();
    #pragma unroll
    for (int off = 128; off >= 1; off >>= 1) {
        if (t < off) {
            float4 u = sh[t + off];
            sh[t].x += u.x; sh[t].y += u.y; sh[t].z += u.z; sh[t].w += u.w;
        }
        __syncthreads();
    }
    if (t == 0) ((float4*)rv)[b] = sh[0];
}

// ---------------- launcher ----------------------------------------------------
extern "C" void kernel_launch(void* const* d_in, const int* in_sizes, int n_in,
                              void* d_out, int out_size) {
    const float* x   = (const float*)d_in[0];
    const float* mem = (const float*)d_in[1];
    const float* Wc  = (const float*)d_in[2];
    const float* bc  = (const float*)d_in[3];
    const float* Wp  = (const float*)d_in[4];
    const float* bp  = (const float*)d_in[5];
    const float* Wo  = (const float*)d_in[6];
    const float* bo  = (const float*)d_in[7];
    const float* rp  = (const float*)d_in[8];
    const float* wrp = (const float*)d_in[9];
    const float* wwp = (const float*)d_in[10];

    float* out     = (float*)d_out;
    float* o_saida = out;                                  // [256]
    float* o_mem   = out + D_OUT;                          // [32768*1024]
    float* o_rv    = o_mem + (size_t)ROWS * COLS;          // [1024]
    float* o_wr    = o_rv + COLS;                          // [32768]
    float* o_ww    = o_wr + ROWS;                          // [32768]

    k_gemv_h<<<D_CTRL / 8, 256>>>(x, rp, Wc, bc);
    k_gemv_p<<<(N_PAR + D_OUT + 7) / 8, 256>>>(Wp, bp, Wo, bo, o_saida);
    k_activ<<<1, 1024>>>();
    k_sim<<<ROWS / 32, 256>>>(mem);
    k_shiftpow<<<dim3(ROWS / 256, 2), 256>>>(wrp, wwp);
    k_final<<<NBF, 256>>>(mem, o_mem, o_wr, o_ww);
    k_rv<<<COLS / 4, 256>>>(o_rv);
}

// round 9
// speedup vs baseline: 1.0139x; 1.0139x over previous
#include <cuda_runtime.h>
#include <math.h>
#include <stdint.h>

#define ROWS    32768
#define COLS    1024
#define D_IN    256
#define D_OUT   256
#define D_CTRL  1024
#define D_CIN   1280      // D_IN + COLS
#define HEADSZ  1030      // COLS + 1 + 1 + 3 + 1
#define N_PAR   4108      // 2*HEADSZ + 2*COLS
#define NBF     2048      // blocks in final pass
#define RPB     16        // rows per block in final pass

// k_sim TMA pipeline geometry
#define SIM_NST     4                     // stages
#define SIM_SROWS   4                     // rows per stage (= warps per block)
#define SIM_STAGE_B (SIM_SROWS * COLS * 4)  // 16384 bytes
#define SIM_CROWS   64                    // rows per block
#define SIM_ITERS   (SIM_CROWS / SIM_SROWS) // 16
#define SIM_SMEM    (1024 + SIM_NST * SIM_STAGE_B) // 66560

// ---------------- device scratch (static: no allocations allowed) -----------
__device__ float g_h[D_CTRL];
__device__ float g_p[N_PAR];
__device__ float g_krn[COLS], g_kwn[COLS], g_e[COLS], g_a[COLS];
__device__ float g_scal[12];          // per head: beta, g, s0, s1, s2, gamma
__device__ float g_red[4];            // sumexp_r, sumexp_w, powsum_r, powsum_w
__device__ float g_z[2][ROWS];        // exp(beta*cos - beta) per head
__device__ float g_wpow[2][ROWS];     // pre-normalization sharpened weights
__device__ float g_part[NBF * COLS];  // read_vec block partials (8 MB)

// ---------------- helpers ----------------------------------------------------
__device__ __forceinline__ float sigmoidf_(float x) { return 1.f / (1.f + expf(-x)); }
__device__ __forceinline__ float softplusf_(float x) { return x > 20.f ? x : log1pf(expf(x)); }

__device__ __forceinline__ float warp_sum(float v) {
    #pragma unroll
    for (int o = 16; o; o >>= 1) v += __shfl_down_sync(0xffffffffu, v, o);
    return v;
}

// block-wide sum for 1024 threads; red must be shared float[33]
__device__ float block_sum_1024(float v, float* red) {
    int t = threadIdx.x;
    v = warp_sum(v);
    if ((t & 31) == 0) red[t >> 5] = v;
    __syncthreads();
    if (t < 32) {
        float u = red[t];
        u = warp_sum(u);
        if (t == 0) red[32] = u;
    }
    __syncthreads();
    return red[32];
}

// ---- mbarrier / bulk-async primitives ----
__device__ __forceinline__ uint32_t smem_u32(const void* p) {
    uint32_t a;
    asm("{ .reg .u64 t; cvta.to.shared.u64 t, %1; cvt.u32.u64 %0, t; }" : "=r"(a) : "l"(p));
    return a;
}
__device__ __forceinline__ void mbar_init(uint32_t a, uint32_t cnt) {
    asm volatile("mbarrier.init.shared.b64 [%0], %1;" :: "r"(a), "r"(cnt) : "memory");
}
__device__ __forceinline__ void mbar_expect_tx(uint32_t a, uint32_t bytes) {
    asm volatile("mbarrier.arrive.expect_tx.shared.b64 _, [%0], %1;" :: "r"(a), "r"(bytes) : "memory");
}
__device__ __forceinline__ void mbar_arrive(uint32_t a) {
    asm volatile("mbarrier.arrive.shared.b64 _, [%0];" :: "r"(a) : "memory");
}
__device__ __forceinline__ void mbar_wait(uint32_t a, uint32_t phase) {
    asm volatile(
        "{\n\t.reg .pred P;\n"
        "W_%=:\n\t"
        "mbarrier.try_wait.parity.acquire.cta.shared::cta.b64 P, [%0], %1, 0x989680;\n\t"
        "@P bra D_%=;\n\t"
        "bra W_%=;\n"
        "D_%=:\n\t}"
        :: "r"(a), "r"(phase) : "memory");
}
__device__ __forceinline__ void bulk_g2s(uint32_t dst_s, const void* src_g,
                                         uint32_t bytes, uint32_t mbar) {
    asm volatile(
        "cp.async.bulk.shared::cta.global.mbarrier::complete_tx::bytes [%0], [%1], %2, [%3];"
        :: "r"(dst_s), "l"(src_g), "r"(bytes), "r"(mbar) : "memory");
}

// ---------------- K1: h = Wc @ [x; read_prev] + bc --------------------------
__global__ void k_gemv_h(const float* __restrict__ x, const float* __restrict__ rp,
                         const float* __restrict__ Wc, const float* __restrict__ bc) {
    int warp = (blockIdx.x * blockDim.x + threadIdx.x) >> 5;
    int lane = threadIdx.x & 31;
    if (warp >= D_CTRL) return;
    const float4* W4 = (const float4*)(Wc + (size_t)warp * D_CIN);
    const float4* x4 = (const float4*)x;
    const float4* r4 = (const float4*)rp;
    float s = 0.f;
    #pragma unroll
    for (int k = 0; k < 10; k++) {
        int c = lane + 32 * k;                 // float4 index 0..319
        float4 w = W4[c];
        float4 v = (c < 64) ? x4[c] : r4[c - 64];
        s += w.x * v.x + w.y * v.y + w.z * v.z + w.w * v.w;
    }
    s = warp_sum(s);
    if (lane == 0) g_h[warp] = s + bc[warp];
}

// ---------------- K2: p = Wp @ h + bp ; saida = sigmoid(Wo @ h + bo) ---------
__global__ void k_gemv_p(const float* __restrict__ Wp, const float* __restrict__ bp,
                         const float* __restrict__ Wo, const float* __restrict__ bo,
                         float* __restrict__ o_saida) {
    int warp = (blockIdx.x * blockDim.x + threadIdx.x) >> 5;
    int lane = threadIdx.x & 31;
    if (warp >= N_PAR + D_OUT) return;
    const float4* W4 = (warp < N_PAR)
        ? (const float4*)(Wp + (size_t)warp * D_CTRL)
        : (const float4*)(Wo + (size_t)(warp - N_PAR) * D_CTRL);
    const float4* h4 = (const float4*)g_h;
    float s = 0.f;
    #pragma unroll
    for (int k = 0; k < 8; k++) {
        int c = lane + 32 * k;
        float4 w = W4[c], v = h4[c];
        s += w.x * v.x + w.y * v.y + w.z * v.z + w.w * v.w;
    }
    s = warp_sum(s);
    if (lane == 0) {
        if (warp < N_PAR) g_p[warp] = s + bp[warp];
        else o_saida[warp - N_PAR] = sigmoidf_(s + bo[warp - N_PAR]);
    }
}

// ---------------- K3: activations, key normalization, scalars, reset reds ---
__global__ void k_activ() {
    __shared__ float red[33];
    int t = threadIdx.x;  // 1024 threads

    float kr = tanhf(g_p[t]);
    float nr = block_sum_1024(kr * kr, red);
    float kw = tanhf(g_p[HEADSZ + t]);
    float nw = block_sum_1024(kw * kw, red);

    g_krn[t] = kr / fmaxf(sqrtf(nr), 1e-12f);
    g_kwn[t] = kw / fmaxf(sqrtf(nw), 1e-12f);
    g_e[t]   = sigmoidf_(g_p[2 * HEADSZ + t]);
    g_a[t]   = tanhf(g_p[2 * HEADSZ + COLS + t]);

    if (t < 2) {
        int o = t * HEADSZ;
        float beta  = softplusf_(g_p[o + COLS]);
        float gg    = sigmoidf_(g_p[o + COLS + 1]);
        float a0 = g_p[o + COLS + 2], a1 = g_p[o + COLS + 3], a2 = g_p[o + COLS + 4];
        float m = fmaxf(a0, fmaxf(a1, a2));
        float e0 = expf(a0 - m), e1 = expf(a1 - m), e2 = expf(a2 - m);
        float inv = 1.f / (e0 + e1 + e2);
        float gamma = softplusf_(g_p[o + COLS + 5]) + 1.f;
        g_scal[t * 6 + 0] = beta;
        g_scal[t * 6 + 1] = gg;
        g_scal[t * 6 + 2] = e0 * inv;
        g_scal[t * 6 + 3] = e1 * inv;
        g_scal[t * 6 + 4] = e2 * inv;
        g_scal[t * 6 + 5] = gamma;
    }
    if (t < 4) g_red[t] = 0.f;
}

// ---------------- K4: similarity pass — cp.async.bulk pipeline --------------
// 128 threads (4 warps) per block, 64 rows per block (grid 512).
// Thread 0 streams 4-row (16 KB) stages into a 4-deep smem ring via
// cp.async.bulk + mbarrier; each warp consumes one row per stage with keys
// held in registers. Loads no longer occupy warp issue slots or registers:
// in-flight bytes = 3 blocks/SM x 4 stages x 16 KB = 192 KB/SM.
__global__ void __launch_bounds__(128, 3) k_sim(const float* __restrict__ mem) {
    extern __shared__ char sm[];
    uint32_t smbase = smem_u32(sm);
    uint32_t full0  = smbase;        // 4 x 8 B
    uint32_t empty0 = smbase + 32;   // 4 x 8 B
    const float4* stages = (const float4*)(sm + 1024);

    int t = threadIdx.x;
    int warp = t >> 5, lane = t & 31;
    int rowbase = blockIdx.x * SIM_CROWS;

    if (t == 0) {
        #pragma unroll
        for (int s = 0; s < SIM_NST; s++) {
            mbar_init(full0 + 8 * s, 1);
            mbar_init(empty0 + 8 * s, SIM_SROWS);
        }
    }
    __syncthreads();

    // keys in registers (each lane owns columns lane+32k)
    float4 kr[8], kw[8];
    #pragma unroll
    for (int k = 0; k < 8; k++) {
        kr[k] = ((const float4*)g_krn)[lane + 32 * k];
        kw[k] = ((const float4*)g_kwn)[lane + 32 * k];
    }
    float br = g_scal[0], bw = g_scal[6];

    // prefetch all stages
    if (t == 0) {
        #pragma unroll
        for (int s = 0; s < SIM_NST; s++) {
            mbar_expect_tx(full0 + 8 * s, SIM_STAGE_B);
            bulk_g2s(smbase + 1024 + s * SIM_STAGE_B,
                     mem + (size_t)(rowbase + s * SIM_SROWS) * COLS,
                     SIM_STAGE_B, full0 + 8 * s);
        }
    }

    float sr = 0.f, sw = 0.f;   // per-warp exp sums (lane 0)

    for (int it = 0; it < SIM_ITERS; it++) {
        int s = it & (SIM_NST - 1);
        uint32_t ph = (it >> 2) & 1;
        mbar_wait(full0 + 8 * s, ph);

        const float4* row = stages + (size_t)s * (SIM_SROWS * 256) + warp * 256;
        float4 a[8];
        #pragma unroll
        for (int k = 0; k < 8; k++) a[k] = row[lane + 32 * k];

        float dr = 0.f, dw = 0.f, ss = 0.f;
        #pragma unroll
        for (int k = 0; k < 8; k++) {
            float4 v = a[k];
            dr += v.x * kr[k].x + v.y * kr[k].y + v.z * kr[k].z + v.w * kr[k].w;
            dw += v.x * kw[k].x + v.y * kw[k].y + v.z * kw[k].z + v.w * kw[k].w;
            ss += v.x * v.x + v.y * v.y + v.z * v.z + v.w * v.w;
        }
        dr = warp_sum(dr); dw = warp_sum(dw); ss = warp_sum(ss);

        if (lane == 0) {
            mbar_arrive(empty0 + 8 * s);   // reads complete (data-dependent)
            int rowg = rowbase + it * SIM_SROWS + warp;
            float inv = 1.f / fmaxf(sqrtf(ss), 1e-12f);
            // z = beta*cos; subtract analytic bound beta (cos <= 1)
            float er = expf(br * dr * inv - br);
            float ew = expf(bw * dw * inv - bw);
            g_z[0][rowg] = er;
            g_z[1][rowg] = ew;
            sr += er; sw += ew;
        }
        if (t == 0 && it + SIM_NST < SIM_ITERS) {
            mbar_wait(empty0 + 8 * s, ph);  // all 4 warps done with slot s
            mbar_expect_tx(full0 + 8 * s, SIM_STAGE_B);
            bulk_g2s(smbase + 1024 + s * SIM_STAGE_B,
                     mem + (size_t)(rowbase + (it + SIM_NST) * SIM_SROWS) * COLS,
                     SIM_STAGE_B, full0 + 8 * s);
        }
    }
    if (lane == 0) {
        atomicAdd(&g_red[0], sr);
        atomicAdd(&g_red[1], sw);
    }
}

// ---------------- K5: gate + circular shift + sharpening (both heads) -------
__global__ void k_shiftpow(const float* __restrict__ wpr, const float* __restrict__ wpw) {
    __shared__ float red[8];
    int head = blockIdx.y;
    int i = blockIdx.x * 256 + threadIdx.x;
    const float* wprev = head ? wpw : wpr;
    const float* z = g_z[head];
    float invsum = 1.f / g_red[head];
    float gg = g_scal[head * 6 + 1];
    float s0 = g_scal[head * 6 + 2], s1 = g_scal[head * 6 + 3], s2 = g_scal[head * 6 + 4];
    float gamma = g_scal[head * 6 + 5];
    float omg = 1.f - gg;

    int im = (i - 1) & (ROWS - 1), ip = (i + 1) & (ROWS - 1);
    float wgm = gg * z[im] * invsum + omg * wprev[im];
    float wg0 = gg * z[i]  * invsum + omg * wprev[i];
    float wgp = gg * z[ip] * invsum + omg * wprev[ip];
    float wt = s0 * wgm + s1 * wg0 + s2 * wgp;   // roll(+1)=i-1, roll(-1)=i+1
    float wp = powf(wt, gamma);
    g_wpow[head][i] = wp;

    wp = warp_sum(wp);
    if ((threadIdx.x & 31) == 0) red[threadIdx.x >> 5] = wp;
    __syncthreads();
    if (threadIdx.x == 0) {
        float s = 0.f;
        #pragma unroll
        for (int w = 0; w < 8; w++) s += red[w];
        atomicAdd(&g_red[2 + head], s);
    }
}

// ---------------- K6: final pass — pipelined, thread-owns-columns -----------
// (champion version, 88.1us run) 16 rows per block (grid 2048), double-buffered.
__global__ void __launch_bounds__(256) k_final(const float* __restrict__ mem,
                                               float* __restrict__ memnew,
                                               float* __restrict__ o_wr,
                                               float* __restrict__ o_ww) {
    int t = threadIdx.x;
    int row0 = blockIdx.x * RPB;
    float inv_r = 1.f / (g_red[2] + 1e-8f);
    float inv_w = 1.f / (g_red[3] + 1e-8f);

    if (t < RPB) {
        int r = row0 + t;
        o_wr[r] = g_wpow[0][r] * inv_r;
        o_ww[r] = g_wpow[1][r] * inv_w;
    }

    float4 e = ((const float4*)g_e)[t];
    float4 a = ((const float4*)g_a)[t];
    float4 acc = make_float4(0.f, 0.f, 0.f, 0.f);

    const float4* m4 = (const float4*)mem + (size_t)row0 * 256 + t;
    float4* o4 = (float4*)memnew + (size_t)row0 * 256 + t;

    float4 buf[2][4];
    #pragma unroll
    for (int j = 0; j < 4; j++) buf[0][j] = __ldcs(m4 + (size_t)j * 256);

    #pragma unroll
    for (int r = 0; r < RPB; r += 4) {
        const int cur = (r >> 2) & 1, nxt = cur ^ 1;
        if (r + 4 < RPB) {
            #pragma unroll
            for (int j = 0; j < 4; j++)
                buf[nxt][j] = __ldcs(m4 + (size_t)(r + 4 + j) * 256);
        }
        #pragma unroll
        for (int j = 0; j < 4; j++) {
            int row = row0 + r + j;
            float wr = g_wpow[0][row] * inv_r;
            float ww = g_wpow[1][row] * inv_w;
            float4 m = buf[cur][j];
            float4 o;
            o.x = m.x * (1.f - ww * e.x) + ww * a.x;
            o.y = m.y * (1.f - ww * e.y) + ww * a.y;
            o.z = m.z * (1.f - ww * e.z) + ww * a.z;
            o.w = m.w * (1.f - ww * e.w) + ww * a.w;
            __stcs(o4 + (size_t)(r + j) * 256, o);
            acc.x += wr * m.x;
            acc.y += wr * m.y;
            acc.z += wr * m.z;
            acc.w += wr * m.w;
        }
    }
    ((float4*)g_part)[(size_t)blockIdx.x * 256 + t] = acc;
}

// ---------------- K7: reduce read_vec partials -------------------------------
__global__ void __launch_bounds__(256) k_rv(float* __restrict__ rv) {
    __shared__ float4 sh[256];
    int b = blockIdx.x;      // 0..255
    int t = threadIdx.x;
    const float4* p4 = (const float4*)g_part;
    float4 s = make_float4(0.f, 0.f, 0.f, 0.f);
    #pragma unroll
    for (int i = 0; i < NBF / 256; i++) {
        float4 v = p4[(size_t)(t + i * 256) * 256 + b];
        s.x += v.x; s.y += v.y; s.z += v.z; s.w += v.w;
    }
    sh[t] = s;
    __syncthreads();
    #pragma unroll
    for (int off = 128; off >= 1; off >>= 1) {
        if (t < off) {
            float4 u = sh[t + off];
            sh[t].x += u.x; sh[t].y += u.y; sh[t].z += u.z; sh[t].w += u.w;
        }
        __syncthreads();
    }
    if (t == 0) ((float4*)rv)[b] = sh[0];
}

// ---------------- launcher ----------------------------------------------------
extern "C" void kernel_launch(void* const* d_in, const int* in_sizes, int n_in,
                              void* d_out, int out_size) {
    const float* x   = (const float*)d_in[0];
    const float* mem = (const float*)d_in[1];
    const float* Wc  = (const float*)d_in[2];
    const float* bc  = (const float*)d_in[3];
    const float* Wp  = (const float*)d_in[4];
    const float* bp  = (const float*)d_in[5];
    const float* Wo  = (const float*)d_in[6];
    const float* bo  = (const float*)d_in[7];
    const float* rp  = (const float*)d_in[8];
    const float* wrp = (const float*)d_in[9];
    const float* wwp = (const float*)d_in[10];

    float* out     = (float*)d_out;
    float* o_saida = out;                                  // [256]
    float* o_mem   = out + D_OUT;                          // [32768*1024]
    float* o_rv    = o_mem + (size_t)ROWS * COLS;          // [1024]
    float* o_wr    = o_rv + COLS;                          // [32768]
    float* o_ww    = o_wr + ROWS;                          // [32768]

    static int smem_set = 0;
    if (!smem_set) {
        cudaFuncSetAttribute(k_sim, cudaFuncAttributeMaxDynamicSharedMemorySize, SIM_SMEM);
        smem_set = 1;
    }

    k_gemv_h<<<D_CTRL / 8, 256>>>(x, rp, Wc, bc);
    k_gemv_p<<<(N_PAR + D_OUT + 7) / 8, 256>>>(Wp, bp, Wo, bo, o_saida);
    k_activ<<<1, 1024>>>();
    k_sim<<<ROWS / SIM_CROWS, 128, SIM_SMEM>>>(mem);
    k_shiftpow<<<dim3(ROWS / 256, 2), 256>>>(wrp, wwp);
    k_final<<<NBF, 256>>>(mem, o_mem, o_wr, o_ww);
    k_rv<<<COLS / 4, 256>>>(o_rv);
}

// round 10
// speedup vs baseline: 1.1102x; 1.0950x over previous
#include <cuda_runtime.h>
#include <math.h>

#define ROWS    32768
#define COLS    1024
#define D_IN    256
#define D_OUT   256
#define D_CTRL  1024
#define D_CIN   1280      // D_IN + COLS
#define HEADSZ  1030      // COLS + 1 + 1 + 3 + 1
#define N_PAR   4108      // 2*HEADSZ + 2*COLS
#define NBF     2048      // blocks in final pass
#define RPB     16        // rows per block in final pass

// ---------------- device scratch (static: no allocations allowed) -----------
__device__ float g_h[D_CTRL];
__device__ float g_p[N_PAR];
__device__ float g_krn[COLS], g_kwn[COLS], g_e[COLS], g_a[COLS];
__device__ float g_scal[12];          // per head: beta, g, s0, s1, s2, gamma
__device__ float g_red[4];            // sumexp_r, sumexp_w, powsum_r, powsum_w
__device__ float g_z[2][ROWS];        // exp(beta*cos - beta) per head
__device__ float g_wpow[2][ROWS];     // pre-normalization sharpened weights
__device__ float g_part[NBF * COLS];  // read_vec block partials (8 MB)

// ---------------- helpers ----------------------------------------------------
__device__ __forceinline__ float sigmoidf_(float x) { return 1.f / (1.f + expf(-x)); }
__device__ __forceinline__ float softplusf_(float x) { return x > 20.f ? x : log1pf(expf(x)); }

// PDL primitives (sm_90+). launch_dependents: allow dependent grid to launch.
// wait: block until the PRIMARY grid completed and its memory is visible.
__device__ __forceinline__ void pdl_launch() {
    asm volatile("griddepcontrol.launch_dependents;");
}
__device__ __forceinline__ void pdl_wait() {
    asm volatile("griddepcontrol.wait;" ::: "memory");
}

__device__ __forceinline__ float warp_sum(float v) {
    #pragma unroll
    for (int o = 16; o; o >>= 1) v += __shfl_down_sync(0xffffffffu, v, o);
    return v;
}

// block-wide sum for 1024 threads; red must be shared float[33]
__device__ float block_sum_1024(float v, float* red) {
    int t = threadIdx.x;
    v = warp_sum(v);
    if ((t & 31) == 0) red[t >> 5] = v;
    __syncthreads();
    if (t < 32) {
        float u = red[t];
        u = warp_sum(u);
        if (t == 0) red[32] = u;
    }
    __syncthreads();
    return red[32];
}

// ---------------- K1: h = Wc @ [x; read_prev] + bc --------------------------
__global__ void k_gemv_h(const float* __restrict__ x, const float* __restrict__ rp,
                         const float* __restrict__ Wc, const float* __restrict__ bc) {
    pdl_launch();   // consumer (gemv_p) prologue reads only Wp — independent
    int warp = (blockIdx.x * blockDim.x + threadIdx.x) >> 5;
    int lane = threadIdx.x & 31;
    if (warp >= D_CTRL) return;
    const float4* W4 = (const float4*)(Wc + (size_t)warp * D_CIN);
    const float4* x4 = (const float4*)x;
    const float4* r4 = (const float4*)rp;
    float s = 0.f;
    #pragma unroll
    for (int k = 0; k < 10; k++) {
        int c = lane + 32 * k;                 // float4 index 0..319
        float4 w = W4[c];
        float4 v = (c < 64) ? x4[c] : r4[c - 64];
        s += w.x * v.x + w.y * v.y + w.z * v.z + w.w * v.w;
    }
    s = warp_sum(s);
    if (lane == 0) g_h[warp] = s + bc[warp];
}

// ---------------- K2: p = Wp @ h + bp ; saida = sigmoid(Wo @ h + bo) ---------
// PDL: loads ALL weight regs before waiting on gemv_h -> the 17MB weight
// stream overlaps gemv_h completely.
__global__ void k_gemv_p(const float* __restrict__ Wp, const float* __restrict__ bp,
                         const float* __restrict__ Wo, const float* __restrict__ bo,
                         float* __restrict__ o_saida) {
    int warp = (blockIdx.x * blockDim.x + threadIdx.x) >> 5;
    int lane = threadIdx.x & 31;
    if (warp >= N_PAR + D_OUT) { pdl_wait(); return; }
    const float4* W4 = (warp < N_PAR)
        ? (const float4*)(Wp + (size_t)warp * D_CTRL)
        : (const float4*)(Wo + (size_t)(warp - N_PAR) * D_CTRL);
    float4 w[8];
    #pragma unroll
    for (int k = 0; k < 8; k++) w[k] = __ldcs(&W4[lane + 32 * k]);

    pdl_wait();   // h must be complete

    const float4* h4 = (const float4*)g_h;
    float s = 0.f;
    #pragma unroll
    for (int k = 0; k < 8; k++) {
        float4 v = h4[lane + 32 * k];
        s += w[k].x * v.x + w[k].y * v.y + w[k].z * v.z + w[k].w * v.w;
    }
    s = warp_sum(s);
    if (lane == 0) {
        if (warp < N_PAR) g_p[warp] = s + bp[warp];
        else o_saida[warp - N_PAR] = sigmoidf_(s + bo[warp - N_PAR]);
    }
}

// ---------------- K3: activations, key normalization, scalars, reset reds ---
__global__ void k_activ() {
    pdl_launch();   // k_sim prologue touches nothing we write
    pdl_wait();     // p must be complete
    __shared__ float red[33];
    int t = threadIdx.x;  // 1024 threads

    float kr = tanhf(g_p[t]);
    float nr = block_sum_1024(kr * kr, red);
    float kw = tanhf(g_p[HEADSZ + t]);
    float nw = block_sum_1024(kw * kw, red);

    g_krn[t] = kr / fmaxf(sqrtf(nr), 1e-12f);
    g_kwn[t] = kw / fmaxf(sqrtf(nw), 1e-12f);
    g_e[t]   = sigmoidf_(g_p[2 * HEADSZ + t]);
    g_a[t]   = tanhf(g_p[2 * HEADSZ + COLS + t]);

    if (t < 2) {
        int o = t * HEADSZ;
        float beta  = softplusf_(g_p[o + COLS]);
        float gg    = sigmoidf_(g_p[o + COLS + 1]);
        float a0 = g_p[o + COLS + 2], a1 = g_p[o + COLS + 3], a2 = g_p[o + COLS + 4];
        float m = fmaxf(a0, fmaxf(a1, a2));
        float e0 = expf(a0 - m), e1 = expf(a1 - m), e2 = expf(a2 - m);
        float inv = 1.f / (e0 + e1 + e2);
        float gamma = softplusf_(g_p[o + COLS + 5]) + 1.f;
        g_scal[t * 6 + 0] = beta;
        g_scal[t * 6 + 1] = gg;
        g_scal[t * 6 + 2] = e0 * inv;
        g_scal[t * 6 + 3] = e1 * inv;
        g_scal[t * 6 + 4] = e2 * inv;
        g_scal[t * 6 + 5] = gamma;
    }
    if (t < 4) g_red[t] = 0.f;
}

// ---------------- K4: similarity pass (128 MB read) --------------------------
// Champion config: keys in smem, 4 rows/warp, k-unroll x2 -> 8 LDG.128 in flight.
__global__ void __launch_bounds__(256) k_sim(const float* __restrict__ mem) {
    pdl_launch();   // shiftpow/final prologues touch only kernel inputs
    pdl_wait();     // activ outputs (keys/scalars) must be complete
    __shared__ float4 skr[256], skw[256];
    __shared__ float ser[8], sew[8];
    int t = threadIdx.x;
    skr[t] = ((const float4*)g_krn)[t];
    skw[t] = ((const float4*)g_kwn)[t];
    __syncthreads();

    int warp = t >> 5, lane = t & 31;
    int row0 = (blockIdx.x * 8 + warp) * 4;
    const float4* m0 = (const float4*)mem + (size_t)row0 * 256;

    float dr[4], dw[4], ss[4];
    #pragma unroll
    for (int j = 0; j < 4; j++) { dr[j] = 0.f; dw[j] = 0.f; ss[j] = 0.f; }

    #pragma unroll
    for (int k = 0; k < 8; k += 2) {
        int c0 = lane + 32 * k, c1 = c0 + 32;
        float4 a[4][2];
        #pragma unroll
        for (int j = 0; j < 4; j++) {
            a[j][0] = __ldcs(&m0[(size_t)j * 256 + c0]);
            a[j][1] = __ldcs(&m0[(size_t)j * 256 + c1]);
        }
        float4 r0 = skr[c0], r1 = skr[c1];
        float4 w0 = skw[c0], w1 = skw[c1];
        #pragma unroll
        for (int j = 0; j < 4; j++) {
            float4 v = a[j][0];
            dr[j] += v.x * r0.x + v.y * r0.y + v.z * r0.z + v.w * r0.w;
            dw[j] += v.x * w0.x + v.y * w0.y + v.z * w0.z + v.w * w0.w;
            ss[j] += v.x * v.x + v.y * v.y + v.z * v.z + v.w * v.w;
            v = a[j][1];
            dr[j] += v.x * r1.x + v.y * r1.y + v.z * r1.z + v.w * r1.w;
            dw[j] += v.x * w1.x + v.y * w1.y + v.z * w1.z + v.w * w1.w;
            ss[j] += v.x * v.x + v.y * v.y + v.z * v.z + v.w * v.w;
        }
    }
    #pragma unroll
    for (int j = 0; j < 4; j++) {
        dr[j] = warp_sum(dr[j]);
        dw[j] = warp_sum(dw[j]);
        ss[j] = warp_sum(ss[j]);
    }
    if (lane == 0) {
        float br = g_scal[0], bw = g_scal[6];
        float sr = 0.f, sw = 0.f;
        #pragma unroll
        for (int j = 0; j < 4; j++) {
            float inv = 1.f / fmaxf(sqrtf(ss[j]), 1e-12f);
            // z = beta*cos; subtract analytic bound beta (cos <= 1) for stability
            float er = expf(br * dr[j] * inv - br);
            float ew = expf(bw * dw[j] * inv - bw);
            g_z[0][row0 + j] = er;
            g_z[1][row0 + j] = ew;
            sr += er; sw += ew;
        }
        ser[warp] = sr; sew[warp] = sw;
    }
    __syncthreads();
    if (t == 0) {
        float sr = 0.f, sw = 0.f;
        #pragma unroll
        for (int i = 0; i < 8; i++) { sr += ser[i]; sw += sew[i]; }
        atomicAdd(&g_red[0], sr);
        atomicAdd(&g_red[1], sw);
    }
}

// ---------------- K5: gate + circular shift + sharpening (both heads) -------
__global__ void k_shiftpow(const float* __restrict__ wpr, const float* __restrict__ wpw) {
    pdl_launch();   // k_final prologue reads only memoria
    __shared__ float red[8];
    int head = blockIdx.y;
    int i = blockIdx.x * 256 + threadIdx.x;
    const float* wprev = head ? wpw : wpr;
    int im = (i - 1) & (ROWS - 1), ip = (i + 1) & (ROWS - 1);
    // prologue: wprev is a kernel input, independent of k_sim
    float pvm = wprev[im], pv0 = wprev[i], pvp = wprev[ip];

    pdl_wait();     // g_z / g_red[0..1] must be complete

    const float* z = g_z[head];
    float invsum = 1.f / g_red[head];
    float gg = g_scal[head * 6 + 1];
    float s0 = g_scal[head * 6 + 2], s1 = g_scal[head * 6 + 3], s2 = g_scal[head * 6 + 4];
    float gamma = g_scal[head * 6 + 5];
    float omg = 1.f - gg;

    float wgm = gg * z[im] * invsum + omg * pvm;
    float wg0 = gg * z[i]  * invsum + omg * pv0;
    float wgp = gg * z[ip] * invsum + omg * pvp;
    float wt = s0 * wgm + s1 * wg0 + s2 * wgp;   // roll(+1)=i-1, roll(-1)=i+1
    float wp = powf(wt, gamma);
    g_wpow[head][i] = wp;

    wp = warp_sum(wp);
    if ((threadIdx.x & 31) == 0) red[threadIdx.x >> 5] = wp;
    __syncthreads();
    if (threadIdx.x == 0) {
        float s = 0.f;
        #pragma unroll
        for (int w = 0; w < 8; w++) s += red[w];
        atomicAdd(&g_red[2 + head], s);
    }
}

// ---------------- K6: final pass — pipelined, thread-owns-columns -----------
// Champion version; prologue (first 4-row prefetch of memoria) hoisted above
// the PDL wait so it overlaps k_shiftpow.
__global__ void __launch_bounds__(256) k_final(const float* __restrict__ mem,
                                               float* __restrict__ memnew,
                                               float* __restrict__ o_wr,
                                               float* __restrict__ o_ww) {
    int t = threadIdx.x;
    int row0 = blockIdx.x * RPB;
    const float4* m4 = (const float4*)mem + (size_t)row0 * 256 + t;
    float4* o4 = (float4*)memnew + (size_t)row0 * 256 + t;

    float4 buf[2][4];
    #pragma unroll
    for (int j = 0; j < 4; j++) buf[0][j] = __ldcs(m4 + (size_t)j * 256);

    pdl_wait();   // g_wpow / g_red[2..3] must be complete

    float inv_r = 1.f / (g_red[2] + 1e-8f);
    float inv_w = 1.f / (g_red[3] + 1e-8f);

    if (t < RPB) {
        int r = row0 + t;
        o_wr[r] = g_wpow[0][r] * inv_r;
        o_ww[r] = g_wpow[1][r] * inv_w;
    }

    float4 e = ((const float4*)g_e)[t];
    float4 a = ((const float4*)g_a)[t];
    float4 acc = make_float4(0.f, 0.f, 0.f, 0.f);

    #pragma unroll
    for (int r = 0; r < RPB; r += 4) {
        const int cur = (r >> 2) & 1, nxt = cur ^ 1;
        if (r + 4 < RPB) {
            #pragma unroll
            for (int j = 0; j < 4; j++)
                buf[nxt][j] = __ldcs(m4 + (size_t)(r + 4 + j) * 256);
        }
        #pragma unroll
        for (int j = 0; j < 4; j++) {
            int row = row0 + r + j;
            float wr = g_wpow[0][row] * inv_r;
            float ww = g_wpow[1][row] * inv_w;
            float4 m = buf[cur][j];
            float4 o;
            o.x = m.x * (1.f - ww * e.x) + ww * a.x;
            o.y = m.y * (1.f - ww * e.y) + ww * a.y;
            o.z = m.z * (1.f - ww * e.z) + ww * a.z;
            o.w = m.w * (1.f - ww * e.w) + ww * a.w;
            __stcs(o4 + (size_t)(r + j) * 256, o);
            acc.x += wr * m.x;
            acc.y += wr * m.y;
            acc.z += wr * m.z;
            acc.w += wr * m.w;
        }
    }
    ((float4*)g_part)[(size_t)blockIdx.x * 256 + t] = acc;
}

// ---------------- K7: reduce read_vec partials -------------------------------
__global__ void __launch_bounds__(256) k_rv(float* __restrict__ rv) {
    pdl_wait();
    __shared__ float4 sh[256];
    int b = blockIdx.x;      // 0..255
    int t = threadIdx.x;
    const float4* p4 = (const float4*)g_part;
    float4 s = make_float4(0.f, 0.f, 0.f, 0.f);
    #pragma unroll
    for (int i = 0; i < NBF / 256; i++) {
        float4 v = p4[(size_t)(t + i * 256) * 256 + b];
        s.x += v.x; s.y += v.y; s.z += v.z; s.w += v.w;
    }
    sh[t] = s;
    __syncthreads();
    #pragma unroll
    for (int off = 128; off >= 1; off >>= 1) {
        if (t < off) {
            float4 u = sh[t + off];
            sh[t].x += u.x; sh[t].y += u.y; sh[t].z += u.z; sh[t].w += u.w;
        }
        __syncthreads();
    }
    if (t == 0) ((float4*)rv)[b] = sh[0];
}

// ---------------- launcher ----------------------------------------------------
template <typename K, typename... Args>
static void launch_pdl(K kernel, dim3 grid, dim3 block, Args... args) {
    cudaLaunchConfig_t cfg = {};
    cfg.gridDim = grid;
    cfg.blockDim = block;
    cfg.dynamicSmemBytes = 0;
    cfg.stream = 0;
    cudaLaunchAttribute attr[1];
    attr[0].id = cudaLaunchAttributeProgrammaticStreamSerialization;
    attr[0].val.programmaticStreamSerializationAllowed = 1;
    cfg.attrs = attr;
    cfg.numAttrs = 1;
    cudaLaunchKernelEx(&cfg, kernel, args...);
}

extern "C" void kernel_launch(void* const* d_in, const int* in_sizes, int n_in,
                              void* d_out, int out_size) {
    const float* x   = (const float*)d_in[0];
    const float* mem = (const float*)d_in[1];
    const float* Wc  = (const float*)d_in[2];
    const float* bc  = (const float*)d_in[3];
    const float* Wp  = (const float*)d_in[4];
    const float* bp  = (const float*)d_in[5];
    const float* Wo  = (const float*)d_in[6];
    const float* bo  = (const float*)d_in[7];
    const float* rp  = (const float*)d_in[8];
    const float* wrp = (const float*)d_in[9];
    const float* wwp = (const float*)d_in[10];

    float* out     = (float*)d_out;
    float* o_saida = out;                                  // [256]
    float* o_mem   = out + D_OUT;                          // [32768*1024]
    float* o_rv    = o_mem + (size_t)ROWS * COLS;          // [1024]
    float* o_wr    = o_rv + COLS;                          // [32768]
    float* o_ww    = o_wr + ROWS;                          // [32768]

    k_gemv_h<<<D_CTRL / 8, 256>>>(x, rp, Wc, bc);
    launch_pdl(k_gemv_p, dim3((N_PAR + D_OUT + 7) / 8), dim3(256), Wp, bp, Wo, bo, o_saida);
    launch_pdl(k_activ, dim3(1), dim3(1024));
    launch_pdl(k_sim, dim3(ROWS / 32), dim3(256), mem);
    launch_pdl(k_shiftpow, dim3(ROWS / 256, 2), dim3(256), wrp, wwp);
    launch_pdl(k_final, dim3(NBF), dim3(256), mem, o_mem, o_wr, o_ww);
    launch_pdl(k_rv, dim3(COLS / 4), dim3(256), o_rv);
}